// round 3
// baseline (speedup 1.0000x reference)
#include <cuda_runtime.h>
#include <cuda_bf16.h>
#include <cstdint>

#define N_NODES 100000
#define N_EDGES 1600000
#define FDIM    128
#define HEADS   8
#define EPS_F   1e-12f
#define ALPHA_F 0.2f

// Static device scratch (no runtime allocation).
// g_sc[n*16 + h]  : h<8 -> s_src[n][h], h>=8 -> s_dst[n][h-8]   (6.4 MB, L2-resident)
// g_ssum[n*8 + h] : per-(node,head) sum of exp(e); inverted in place by inv_kernel
// g_ex[e*8 + h]   : stashed exp(e) per edge/head (51.2 MB) — computed once in
//                   sum_kernel, reused in out_kernel (kills the 2nd gather pass)
__device__ __align__(16) float g_sc[N_NODES * 16];
__device__ __align__(16) float g_ssum[N_NODES * 8];
__device__ __align__(16) float g_ex[(size_t)N_EDGES * 8];

// ---------------------------------------------------------------------------
// Kernel 1: per-node scores. One warp per node (grid-stride loop).
// aa in 64 regs/lane; value-splitting reduction: 17 shuffles/node (vs 80).
// Also zero-initializes g_ssum.
// ---------------------------------------------------------------------------
__global__ void __launch_bounds__(256) scores_kernel(
    const float* __restrict__ x,
    const float* __restrict__ aa,
    int n_nodes)
{
    const int lane  = threadIdx.x & 31;
    const int gwarp = (blockIdx.x * blockDim.x + threadIdx.x) >> 5;
    const int nwarp = (gridDim.x * blockDim.x) >> 5;

    float4 areg[16];
    const float4* aa4 = reinterpret_cast<const float4*>(aa);
#pragma unroll
    for (int h = 0; h < HEADS; h++) {
        areg[h]         = __ldg(&aa4[h * 64 + lane]);        // a_src[h]
        areg[HEADS + h] = __ldg(&aa4[h * 64 + 32 + lane]);   // a_dst[h]
    }

    const float4* x4 = reinterpret_cast<const float4*>(x);

    for (int node = gwarp; node < n_nodes; node += nwarp) {
        float4 xv = __ldg(&x4[(size_t)node * 32 + lane]);

        float acc[16];
#pragma unroll
        for (int i = 0; i < 16; i++)
            acc[i] = xv.x * areg[i].x + xv.y * areg[i].y
                   + xv.z * areg[i].z + xv.w * areg[i].w;

        // Value-splitting reduction: each round trades half the values.
#define RSTEP(OFF, NV)                                                     \
        {                                                                  \
            const int kb = (lane & (OFF)) ? (NV) : 0;                      \
            const int gb = (NV) - kb;                                      \
            _Pragma("unroll")                                              \
            for (int i = 0; i < (NV); i++) {                               \
                float give = acc[gb + i];                                  \
                float recv = __shfl_xor_sync(0xffffffffu, give, (OFF));    \
                acc[i] = acc[kb + i] + recv;                               \
            }                                                              \
        }
        RSTEP(16, 8)
        RSTEP(8, 4)
        RSTEP(4, 2)
        RSTEP(2, 1)
#undef RSTEP
        float r = acc[0] + __shfl_xor_sync(0xffffffffu, acc[0], 1);

        if (!(lane & 1)) {
            g_sc[(size_t)node * 16 + (lane >> 1)] = r;      // 16 even lanes
        } else if (lane < 16) {
            g_ssum[(size_t)node * 8 + (lane >> 1)] = 0.0f;  // 8 odd lanes: init
        }
    }
}

// ---------------------------------------------------------------------------
// Per-edge scores -> exp. Only called in sum_kernel now.
// ---------------------------------------------------------------------------
__device__ __forceinline__ void edge_exp(int r, int c, float4& ex0, float4& ex1)
{
    const float4* sc4 = reinterpret_cast<const float4*>(g_sc);
    float4 a0 = __ldg(&sc4[(size_t)r * 4 + 0]);
    float4 a1 = __ldg(&sc4[(size_t)r * 4 + 1]);
    float4 b0 = __ldg(&sc4[(size_t)c * 4 + 2]);
    float4 b1 = __ldg(&sc4[(size_t)c * 4 + 3]);

    float e0x = a0.x + b0.x, e0y = a0.y + b0.y, e0z = a0.z + b0.z, e0w = a0.w + b0.w;
    float e1x = a1.x + b1.x, e1y = a1.y + b1.y, e1z = a1.z + b1.z, e1w = a1.w + b1.w;

    e0x = fmaxf(e0x, ALPHA_F * e0x); e0y = fmaxf(e0y, ALPHA_F * e0y);
    e0z = fmaxf(e0z, ALPHA_F * e0z); e0w = fmaxf(e0w, ALPHA_F * e0w);
    e1x = fmaxf(e1x, ALPHA_F * e1x); e1y = fmaxf(e1y, ALPHA_F * e1y);
    e1z = fmaxf(e1z, ALPHA_F * e1z); e1w = fmaxf(e1w, ALPHA_F * e1w);

    ex0 = make_float4(__expf(e0x), __expf(e0y), __expf(e0z), __expf(e0w));
    ex1 = make_float4(__expf(e1x), __expf(e1y), __expf(e1z), __expf(e1w));
}

// ---------------------------------------------------------------------------
// Kernel 2: compute ex once; segment-sum via red.v4; stash ex (coalesced).
// ---------------------------------------------------------------------------
__global__ void __launch_bounds__(256) sum_kernel(
    const int* __restrict__ row,
    const int* __restrict__ col,
    int n_edges)
{
    int e = blockIdx.x * blockDim.x + threadIdx.x;
    if (e >= n_edges) return;
    int r = __ldg(row + e);
    int c = __ldg(col + e);

    float4 ex0, ex1;
    edge_exp(r, c, ex0, ex1);

    float* dst = g_ssum + (size_t)r * 8;
    asm volatile("red.global.add.v4.f32 [%0], {%1,%2,%3,%4};"
                 :: "l"(dst),     "f"(ex0.x), "f"(ex0.y), "f"(ex0.z), "f"(ex0.w)
                 : "memory");
    asm volatile("red.global.add.v4.f32 [%0], {%1,%2,%3,%4};"
                 :: "l"(dst + 4), "f"(ex1.x), "f"(ex1.y), "f"(ex1.z), "f"(ex1.w)
                 : "memory");

    float4* exb = reinterpret_cast<float4*>(g_ex) + (size_t)e * 2;
    exb[0] = ex0;
    exb[1] = ex1;
}

// ---------------------------------------------------------------------------
// Kernel 2.5: invert sums in place: g_ssum = 1/(g_ssum + EPS).
// ---------------------------------------------------------------------------
__global__ void __launch_bounds__(256) inv_kernel(int n4)  // n4 = N_NODES*8/4
{
    int i = blockIdx.x * blockDim.x + threadIdx.x;
    if (i >= n4) return;
    float4* p = reinterpret_cast<float4*>(g_ssum);
    float4 v = p[i];
    v.x = __frcp_rn(v.x + EPS_F);
    v.y = __frcp_rn(v.y + EPS_F);
    v.z = __frcp_rn(v.z + EPS_F);
    v.w = __frcp_rn(v.w + EPS_F);
    p[i] = v;
}

// ---------------------------------------------------------------------------
// Kernel 3: a[h][e] = ex_stash * inv_ssum[row][h], head-major coalesced write.
// Only remaining gather: 2x float4 from g_ssum (3.2MB, L2-resident).
// ---------------------------------------------------------------------------
__global__ void __launch_bounds__(256) out_kernel(
    const int* __restrict__ row,
    float* __restrict__ out,
    int n_edges)
{
    int e = blockIdx.x * blockDim.x + threadIdx.x;
    if (e >= n_edges) return;
    int r = __ldg(row + e);

    const float4* exb = reinterpret_cast<const float4*>(g_ex) + (size_t)e * 2;
    float4 ex0 = exb[0];
    float4 ex1 = exb[1];

    const float4* ss4 = reinterpret_cast<const float4*>(g_ssum);
    float4 s0 = __ldg(&ss4[(size_t)r * 2 + 0]);
    float4 s1 = __ldg(&ss4[(size_t)r * 2 + 1]);

    size_t E = (size_t)n_edges;
    out[0 * E + e] = ex0.x * s0.x;
    out[1 * E + e] = ex0.y * s0.y;
    out[2 * E + e] = ex0.z * s0.z;
    out[3 * E + e] = ex0.w * s0.w;
    out[4 * E + e] = ex1.x * s1.x;
    out[5 * E + e] = ex1.y * s1.y;
    out[6 * E + e] = ex1.z * s1.z;
    out[7 * E + e] = ex1.w * s1.w;
}

extern "C" void kernel_launch(void* const* d_in, const int* in_sizes, int n_in,
                              void* d_out, int out_size)
{
    const float* x   = (const float*)d_in[0];
    const int*   row = (const int*)  d_in[1];
    const int*   col = (const int*)  d_in[2];
    const float* aa  = (const float*)d_in[3];
    float* out = (float*)d_out;

    int n_nodes = in_sizes[0] / FDIM;   // 100000
    int n_edges = in_sizes[1];          // 1600000

    scores_kernel<<<1184, 256>>>(x, aa, n_nodes);
    sum_kernel<<<(n_edges + 255) / 256, 256>>>(row, col, n_edges);
    {
        int n4 = n_nodes * HEADS / 4;
        inv_kernel<<<(n4 + 255) / 256, 256>>>(n4);
    }
    out_kernel<<<(n_edges + 255) / 256, 256>>>(row, out, n_edges);
}

// round 4
// speedup vs baseline: 1.8111x; 1.8111x over previous
#include <cuda_runtime.h>
#include <cuda_bf16.h>
#include <cstdint>

#define N_NODES 100000
#define N_EDGES 1600000
#define FDIM    128
#define HEADS   8
#define EPS_F   1e-12f
#define ALPHA_F 0.2f

// Static device scratch (no runtime allocation).
// g_sc[n*16 + h]  : h<8 -> s_src[n][h], h>=8 -> s_dst[n][h-8]   (6.4 MB, L2-resident)
// g_ssum[n*8 + h] : per-(node,head) sum of exp(e); inverted in place by inv_kernel
__device__ __align__(16) float g_sc[N_NODES * 16];
__device__ __align__(16) float g_ssum[N_NODES * 8];

// ---------------------------------------------------------------------------
// Kernel 1: per-node scores. One warp per node (grid-stride loop).
// aa in 64 regs/lane. Value-splitting reduction with COMPILE-TIME register
// indices (constant-index selects on a lane-bit predicate) — no dynamic
// register indexing, so no local-memory spill. 15 SHFL per node.
// Final mapping: lanes 2v and 2v+1 hold value v (v = (lane>>1)&15).
// Also zero-initializes g_ssum.
// ---------------------------------------------------------------------------
__global__ void __launch_bounds__(256) scores_kernel(
    const float* __restrict__ x,
    const float* __restrict__ aa,
    int n_nodes)
{
    const int lane  = threadIdx.x & 31;
    const int gwarp = (blockIdx.x * blockDim.x + threadIdx.x) >> 5;
    const int nwarp = (gridDim.x * blockDim.x) >> 5;

    // areg[i] = row i of aa (i<8: a_src[i], i>=8: a_dst[i-8]),
    // features [4*lane, 4*lane+4). 16 float4 = 64 registers.
    float4 areg[16];
    const float4* aa4 = reinterpret_cast<const float4*>(aa);
#pragma unroll
    for (int h = 0; h < HEADS; h++) {
        areg[h]         = __ldg(&aa4[h * 64 + lane]);        // a_src[h]
        areg[HEADS + h] = __ldg(&aa4[h * 64 + 32 + lane]);   // a_dst[h]
    }

    const bool b16 = (lane & 16) != 0;
    const bool b8  = (lane & 8)  != 0;
    const bool b4  = (lane & 4)  != 0;
    const bool b2  = (lane & 2)  != 0;

    const float4* x4 = reinterpret_cast<const float4*>(x);

    for (int node = gwarp; node < n_nodes; node += nwarp) {
        float4 xv = __ldg(&x4[(size_t)node * 32 + lane]);

        float acc[16];
#pragma unroll
        for (int i = 0; i < 16; i++)
            acc[i] = xv.x * areg[i].x + xv.y * areg[i].y
                   + xv.z * areg[i].z + xv.w * areg[i].w;

        // Round 1 (xor 16): keep 8 values. Lo lanes keep v0..7, hi keep v8..15.
#pragma unroll
        for (int i = 0; i < 8; i++) {
            float give = b16 ? acc[i]     : acc[i + 8];
            float keep = b16 ? acc[i + 8] : acc[i];
            acc[i] = keep + __shfl_xor_sync(0xffffffffu, give, 16);
        }
        // Round 2 (xor 8): keep 4.
#pragma unroll
        for (int i = 0; i < 4; i++) {
            float give = b8 ? acc[i]     : acc[i + 4];
            float keep = b8 ? acc[i + 4] : acc[i];
            acc[i] = keep + __shfl_xor_sync(0xffffffffu, give, 8);
        }
        // Round 3 (xor 4): keep 2.
#pragma unroll
        for (int i = 0; i < 2; i++) {
            float give = b4 ? acc[i]     : acc[i + 2];
            float keep = b4 ? acc[i + 2] : acc[i];
            acc[i] = keep + __shfl_xor_sync(0xffffffffu, give, 4);
        }
        // Round 4 (xor 2): keep 1.
        {
            float give = b2 ? acc[0] : acc[1];
            float keep = b2 ? acc[1] : acc[0];
            acc[0] = keep + __shfl_xor_sync(0xffffffffu, give, 2);
        }
        // Round 5 (xor 1): full sum of value v = (lane>>1)&15 on lanes 2v,2v+1.
        float r = acc[0] + __shfl_xor_sync(0xffffffffu, acc[0], 1);

        if (!(lane & 1)) {
            g_sc[(size_t)node * 16 + (lane >> 1)] = r;      // 16 even lanes
        } else if (lane < 16) {
            g_ssum[(size_t)node * 8 + (lane >> 1)] = 0.0f;  // 8 odd lanes: init
        }
    }
}

// ---------------------------------------------------------------------------
// Per-edge scores -> exp: e = lrelu(s_src[r][h] + s_dst[c][h]); ex = exp(e).
// Identical sequence in sum & out kernels so numerator/denominator match.
// ---------------------------------------------------------------------------
__device__ __forceinline__ void edge_exp(int r, int c, float4& ex0, float4& ex1)
{
    const float4* sc4 = reinterpret_cast<const float4*>(g_sc);
    float4 a0 = __ldg(&sc4[(size_t)r * 4 + 0]);
    float4 a1 = __ldg(&sc4[(size_t)r * 4 + 1]);
    float4 b0 = __ldg(&sc4[(size_t)c * 4 + 2]);
    float4 b1 = __ldg(&sc4[(size_t)c * 4 + 3]);

    float e0x = a0.x + b0.x, e0y = a0.y + b0.y, e0z = a0.z + b0.z, e0w = a0.w + b0.w;
    float e1x = a1.x + b1.x, e1y = a1.y + b1.y, e1z = a1.z + b1.z, e1w = a1.w + b1.w;

    e0x = fmaxf(e0x, ALPHA_F * e0x); e0y = fmaxf(e0y, ALPHA_F * e0y);
    e0z = fmaxf(e0z, ALPHA_F * e0z); e0w = fmaxf(e0w, ALPHA_F * e0w);
    e1x = fmaxf(e1x, ALPHA_F * e1x); e1y = fmaxf(e1y, ALPHA_F * e1y);
    e1z = fmaxf(e1z, ALPHA_F * e1z); e1w = fmaxf(e1w, ALPHA_F * e1w);

    ex0 = make_float4(__expf(e0x), __expf(e0y), __expf(e0z), __expf(e0w));
    ex1 = make_float4(__expf(e1x), __expf(e1y), __expf(e1z), __expf(e1w));
}

// ---------------------------------------------------------------------------
// Kernel 2: segment-sum of exp(e) via vectorized L2-side reductions.
// ---------------------------------------------------------------------------
__global__ void __launch_bounds__(256) sum_kernel(
    const int* __restrict__ row,
    const int* __restrict__ col,
    int n_edges)
{
    int e = blockIdx.x * blockDim.x + threadIdx.x;
    if (e >= n_edges) return;
    int r = __ldg(row + e);
    int c = __ldg(col + e);

    float4 ex0, ex1;
    edge_exp(r, c, ex0, ex1);

    float* dst = g_ssum + (size_t)r * 8;
    asm volatile("red.global.add.v4.f32 [%0], {%1,%2,%3,%4};"
                 :: "l"(dst),     "f"(ex0.x), "f"(ex0.y), "f"(ex0.z), "f"(ex0.w)
                 : "memory");
    asm volatile("red.global.add.v4.f32 [%0], {%1,%2,%3,%4};"
                 :: "l"(dst + 4), "f"(ex1.x), "f"(ex1.y), "f"(ex1.z), "f"(ex1.w)
                 : "memory");
}

// ---------------------------------------------------------------------------
// Kernel 2.5: invert sums in place: g_ssum = 1/(g_ssum + EPS).
// ---------------------------------------------------------------------------
__global__ void __launch_bounds__(256) inv_kernel(int n4)  // n4 = N_NODES*8/4
{
    int i = blockIdx.x * blockDim.x + threadIdx.x;
    if (i >= n4) return;
    float4* p = reinterpret_cast<float4*>(g_ssum);
    float4 v = p[i];
    v.x = __frcp_rn(v.x + EPS_F);
    v.y = __frcp_rn(v.y + EPS_F);
    v.z = __frcp_rn(v.z + EPS_F);
    v.w = __frcp_rn(v.w + EPS_F);
    p[i] = v;
}

// ---------------------------------------------------------------------------
// Kernel 3: a[h][e] = exp(e) * inv_ssum[row][h], head-major coalesced write.
// ---------------------------------------------------------------------------
__global__ void __launch_bounds__(256) out_kernel(
    const int* __restrict__ row,
    const int* __restrict__ col,
    float* __restrict__ out,
    int n_edges)
{
    int e = blockIdx.x * blockDim.x + threadIdx.x;
    if (e >= n_edges) return;
    int r = __ldg(row + e);
    int c = __ldg(col + e);

    float4 ex0, ex1;
    edge_exp(r, c, ex0, ex1);

    const float4* ss4 = reinterpret_cast<const float4*>(g_ssum);
    float4 s0 = __ldg(&ss4[(size_t)r * 2 + 0]);
    float4 s1 = __ldg(&ss4[(size_t)r * 2 + 1]);

    size_t E = (size_t)n_edges;
    out[0 * E + e] = ex0.x * s0.x;
    out[1 * E + e] = ex0.y * s0.y;
    out[2 * E + e] = ex0.z * s0.z;
    out[3 * E + e] = ex0.w * s0.w;
    out[4 * E + e] = ex1.x * s1.x;
    out[5 * E + e] = ex1.y * s1.y;
    out[6 * E + e] = ex1.z * s1.z;
    out[7 * E + e] = ex1.w * s1.w;
}

extern "C" void kernel_launch(void* const* d_in, const int* in_sizes, int n_in,
                              void* d_out, int out_size)
{
    const float* x   = (const float*)d_in[0];
    const int*   row = (const int*)  d_in[1];
    const int*   col = (const int*)  d_in[2];
    const float* aa  = (const float*)d_in[3];
    float* out = (float*)d_out;

    int n_nodes = in_sizes[0] / FDIM;   // 100000
    int n_edges = in_sizes[1];          // 1600000

    scores_kernel<<<1184, 256>>>(x, aa, n_nodes);
    sum_kernel<<<(n_edges + 255) / 256, 256>>>(row, col, n_edges);
    {
        int n4 = n_nodes * HEADS / 4;
        inv_kernel<<<(n4 + 255) / 256, 256>>>(n4);
    }
    out_kernel<<<(n_edges + 255) / 256, 256>>>(row, col, out, n_edges);
}

// round 5
// speedup vs baseline: 2.0472x; 1.1303x over previous
#include <cuda_runtime.h>
#include <cuda_bf16.h>
#include <cstdint>

#define N_NODES 100000
#define N_EDGES 1600000
#define FDIM    128
#define HEADS   8
#define EPS_F   1e-12f
#define ALPHA_F 0.2f

// Static device scratch (no runtime allocation).
// g_sc[n*16 + h]  : h<8 -> s_src[n][h], h>=8 -> s_dst[n][h-8]   (6.4 MB, L2-resident)
// g_ssum[n*8 + h] : per-(node,head) sum of exp(e); inverted in place by inv_kernel
__device__ __align__(16) float g_sc[N_NODES * 16];
__device__ __align__(16) float g_ssum[N_NODES * 8];

// ---------------------------------------------------------------------------
// Kernel 1: per-node scores. One warp per node (grid-stride loop).
// aa in 64 regs/lane; value-splitting reduction with compile-time register
// indices (no local-memory spill); 16 SHFL per node.
// Also zero-initializes g_ssum.
// ---------------------------------------------------------------------------
__global__ void __launch_bounds__(256) scores_kernel(
    const float* __restrict__ x,
    const float* __restrict__ aa,
    int n_nodes)
{
    const int lane  = threadIdx.x & 31;
    const int gwarp = (blockIdx.x * blockDim.x + threadIdx.x) >> 5;
    const int nwarp = (gridDim.x * blockDim.x) >> 5;

    float4 areg[16];
    const float4* aa4 = reinterpret_cast<const float4*>(aa);
#pragma unroll
    for (int h = 0; h < HEADS; h++) {
        areg[h]         = __ldg(&aa4[h * 64 + lane]);        // a_src[h]
        areg[HEADS + h] = __ldg(&aa4[h * 64 + 32 + lane]);   // a_dst[h]
    }

    const bool b16 = (lane & 16) != 0;
    const bool b8  = (lane & 8)  != 0;
    const bool b4  = (lane & 4)  != 0;
    const bool b2  = (lane & 2)  != 0;

    const float4* x4 = reinterpret_cast<const float4*>(x);

    for (int node = gwarp; node < n_nodes; node += nwarp) {
        float4 xv = __ldg(&x4[(size_t)node * 32 + lane]);

        float acc[16];
#pragma unroll
        for (int i = 0; i < 16; i++)
            acc[i] = xv.x * areg[i].x + xv.y * areg[i].y
                   + xv.z * areg[i].z + xv.w * areg[i].w;

#pragma unroll
        for (int i = 0; i < 8; i++) {
            float give = b16 ? acc[i]     : acc[i + 8];
            float keep = b16 ? acc[i + 8] : acc[i];
            acc[i] = keep + __shfl_xor_sync(0xffffffffu, give, 16);
        }
#pragma unroll
        for (int i = 0; i < 4; i++) {
            float give = b8 ? acc[i]     : acc[i + 4];
            float keep = b8 ? acc[i + 4] : acc[i];
            acc[i] = keep + __shfl_xor_sync(0xffffffffu, give, 8);
        }
#pragma unroll
        for (int i = 0; i < 2; i++) {
            float give = b4 ? acc[i]     : acc[i + 2];
            float keep = b4 ? acc[i + 2] : acc[i];
            acc[i] = keep + __shfl_xor_sync(0xffffffffu, give, 4);
        }
        {
            float give = b2 ? acc[0] : acc[1];
            float keep = b2 ? acc[1] : acc[0];
            acc[0] = keep + __shfl_xor_sync(0xffffffffu, give, 2);
        }
        float r = acc[0] + __shfl_xor_sync(0xffffffffu, acc[0], 1);

        if (!(lane & 1)) {
            g_sc[(size_t)node * 16 + (lane >> 1)] = r;      // 16 even lanes
        } else if (lane < 16) {
            g_ssum[(size_t)node * 8 + (lane >> 1)] = 0.0f;  // 8 odd lanes: init
        }
    }
}

// ---------------------------------------------------------------------------
// Half-edge exp: thread handles heads [4h, 4h+4) of edge e.
// The two lanes of an edge load adjacent 16B -> coalesce to one 128B line
// per endpoint per edge (halves L1tex gather wavefronts vs 1-thread/edge).
// ---------------------------------------------------------------------------
__device__ __forceinline__ float4 half_edge_exp(int r, int c, int h)
{
    const float4* sc4 = reinterpret_cast<const float4*>(g_sc);
    float4 a = __ldg(&sc4[(size_t)r * 4 + h]);        // src heads 4h..4h+3
    float4 b = __ldg(&sc4[(size_t)c * 4 + 2 + h]);    // dst heads 4h..4h+3

    float ex = a.x + b.x, ey = a.y + b.y, ez = a.z + b.z, ew = a.w + b.w;
    ex = fmaxf(ex, ALPHA_F * ex); ey = fmaxf(ey, ALPHA_F * ey);
    ez = fmaxf(ez, ALPHA_F * ez); ew = fmaxf(ew, ALPHA_F * ew);
    return make_float4(__expf(ex), __expf(ey), __expf(ez), __expf(ew));
}

// ---------------------------------------------------------------------------
// Kernel 2: segment-sum of exp(e). Two threads per edge, one red.v4 each.
// ---------------------------------------------------------------------------
__global__ void __launch_bounds__(256) sum_kernel(
    const int* __restrict__ row,
    const int* __restrict__ col,
    int n_edges)
{
    int t = blockIdx.x * blockDim.x + threadIdx.x;
    int e = t >> 1;
    int h = t & 1;
    if (e >= n_edges) return;
    int r = __ldg(row + e);
    int c = __ldg(col + e);

    float4 exv = half_edge_exp(r, c, h);

    float* dst = g_ssum + (size_t)r * 8 + 4 * h;
    asm volatile("red.global.add.v4.f32 [%0], {%1,%2,%3,%4};"
                 :: "l"(dst), "f"(exv.x), "f"(exv.y), "f"(exv.z), "f"(exv.w)
                 : "memory");
}

// ---------------------------------------------------------------------------
// Kernel 2.5: invert sums in place: g_ssum = 1/(g_ssum + EPS).
// ---------------------------------------------------------------------------
__global__ void __launch_bounds__(256) inv_kernel(int n4)  // n4 = N_NODES*8/4
{
    int i = blockIdx.x * blockDim.x + threadIdx.x;
    if (i >= n4) return;
    float4* p = reinterpret_cast<float4*>(g_ssum);
    float4 v = p[i];
    v.x = __frcp_rn(v.x + EPS_F);
    v.y = __frcp_rn(v.y + EPS_F);
    v.z = __frcp_rn(v.z + EPS_F);
    v.w = __frcp_rn(v.w + EPS_F);
    p[i] = v;
}

// ---------------------------------------------------------------------------
// Kernel 3: a[head][e] = exp * inv_ssum[r][head]. Two threads per edge.
// Per edge-half: 1 wf src gather + 1 wf dst gather + 1 wf ssum gather
// (shared with partner lane) -> 3 wf/edge total vs 6 before.
// ---------------------------------------------------------------------------
__global__ void __launch_bounds__(256) out_kernel(
    const int* __restrict__ row,
    const int* __restrict__ col,
    float* __restrict__ out,
    int n_edges)
{
    int t = blockIdx.x * blockDim.x + threadIdx.x;
    int e = t >> 1;
    int h = t & 1;
    if (e >= n_edges) return;
    int r = __ldg(row + e);
    int c = __ldg(col + e);

    float4 exv = half_edge_exp(r, c, h);

    const float4* ss4 = reinterpret_cast<const float4*>(g_ssum);
    float4 s = __ldg(&ss4[(size_t)r * 2 + h]);

    size_t E = (size_t)n_edges;
    float* o = out + (size_t)(4 * h) * E + e;
    o[0 * E] = exv.x * s.x;
    o[1 * E] = exv.y * s.y;
    o[2 * E] = exv.z * s.z;
    o[3 * E] = exv.w * s.w;
}

extern "C" void kernel_launch(void* const* d_in, const int* in_sizes, int n_in,
                              void* d_out, int out_size)
{
    const float* x   = (const float*)d_in[0];
    const int*   row = (const int*)  d_in[1];
    const int*   col = (const int*)  d_in[2];
    const float* aa  = (const float*)d_in[3];
    float* out = (float*)d_out;

    int n_nodes = in_sizes[0] / FDIM;   // 100000
    int n_edges = in_sizes[1];          // 1600000

    scores_kernel<<<1184, 256>>>(x, aa, n_nodes);

    int nthreads = 2 * n_edges;
    sum_kernel<<<(nthreads + 255) / 256, 256>>>(row, col, n_edges);
    {
        int n4 = n_nodes * HEADS / 4;
        inv_kernel<<<(n4 + 255) / 256, 256>>>(n4);
    }
    out_kernel<<<(nthreads + 255) / 256, 256>>>(row, col, out, n_edges);
}